// round 15
// baseline (speedup 1.0000x reference)
#include <cuda_runtime.h>
#include <cuda_fp16.h>
#include <math.h>
#include <stdint.h>

#define BATCH 4096
#define SQ    64
#define DM    256
#define NH    8
#define FFD   1024
#define NL    6
#define MTOK  (BATCH*SQ)   /* 262144 */

// ---------------- scratch (no allocations allowed) ----------------
__device__ float  g_x[MTOK*DM];          // y2 stream (embed x / post-ff2 pre-LN)
__device__ __align__(16) __half g_qkv16[MTOK*3*DM];
__device__ float  g_o[MTOK*DM];          // attn out; final materialized x at end
__device__ float  g_y[MTOK*DM];          // y1 stream (post-attn pre-LN)
__device__ float  g_ffb[MTOK*FFD];
__device__ float  g_pe[SQ*DM];
__device__ float  g_pooled[BATCH*DM];
__device__ float  g_vh[BATCH*DM];
__device__ float  g_ch[BATCH*DM];
__device__ float  g_h1[BATCH*1024];
__device__ float  g_h1a[BATCH*1024];
__device__ float  g_h1b[BATCH*1024];
__device__ float2 g_st1[MTOK];           // ln1 stats (mean, rstd)
__device__ float2 g_st2[MTOK];           // ln2 stats

// fp16 weight pool (offsets in halfs)
#define OFF_QKV 0UL
#define OFF_OUT 1179648UL
#define OFF_FF1 1572864UL
#define OFF_FF2 3145728UL
#define OFF_VW1 4718592UL
#define OFF_CW1 4784128UL
#define OFF_PW1 4849664UL
#define OFF_PW2 21626880UL
#define WPOOL   25821184UL
__device__ __align__(16) __half g_w16[WPOOL];

// ---------------- fp16 helpers ----------------
__device__ __forceinline__ uint32_t packh(float a, float b) {
    __half2 t = __floats2half2_rn(a, b);
    return *(uint32_t*)&t;
}

__device__ __forceinline__ void cvt_split2u(float x, float y, uint32_t& hi, uint32_t& lo) {
    __half hx = __float2half(x);
    __half hy = __float2half(y);
    hi = ((uint32_t)__half_as_ushort(hy) << 16) | (uint32_t)__half_as_ushort(hx);
    lo = packh(x - __half2float(hx), y - __half2float(hy));
}

__device__ __forceinline__ void mma_f16(float* c, const uint32_t* a, const uint32_t* b) {
    asm volatile(
        "mma.sync.aligned.m16n8k16.row.col.f32.f16.f16.f32 "
        "{%0,%1,%2,%3}, {%4,%5,%6,%7}, {%8,%9}, {%0,%1,%2,%3};\n"
        : "+f"(c[0]), "+f"(c[1]), "+f"(c[2]), "+f"(c[3])
        : "r"(a[0]), "r"(a[1]), "r"(a[2]), "r"(a[3]), "r"(b[0]), "r"(b[1]));
}

// ---------------- weight fp32 -> fp16 ----------------
__global__ void wcvt_kernel(const float* __restrict__ in, __half* __restrict__ o, int n4) {
    int i = blockIdx.x * 256 + threadIdx.x;
    if (i >= n4) return;
    float4 v = ((const float4*)in)[i];
    uint2 w = make_uint2(packh(v.x, v.y), packh(v.z, v.w));
    *(uint2*)&o[(size_t)i * 4] = w;
}

// ---------------- PE precompute ----------------
__global__ void pe_kernel(float* __restrict__ pe) {
    int s = blockIdx.x, d = threadIdx.x;
    int row = s >> 3, col = s & 7;
    int m = d >> 1;
    float div = powf(10000.0f, (2.0f * (float)m) / 256.0f);
    float v = (d & 1) ? cosf((float)col / div) : sinf((float)row / div);
    pe[s * DM + d] = v;
}

// ---------------- tokens + embedding + PE ----------------
__global__ void embed_kernel(const float* __restrict__ board,
                             const float* __restrict__ emb,
                             const float* __restrict__ pe,
                             float* __restrict__ x) {
    int tokidx = blockIdx.x;
    int b = tokidx >> 6, s = tokidx & 63;
    __shared__ float ch[14];
    __shared__ int tok;
    int d = threadIdx.x;
    if (d < 14) ch[d] = board[(size_t)b * 896 + (size_t)d * 64 + s];
    __syncthreads();
    if (d == 0) {
        float mx = ch[0]; int idx = 0;
        #pragma unroll
        for (int c = 1; c < 14; c++) { if (ch[c] > mx) { mx = ch[c]; idx = c; } }
        tok = (mx > 0.0f) ? (idx + 1) : 0;
    }
    __syncthreads();
    x[(size_t)tokidx * DM + d] = emb[tok * DM + d] + pe[s * DM + d];
}

// ---------------- fp16 2-term GEMM, double-buffered, optional fused LN ----------
// C = LN_A(A) @ W^T + bias (+ LN_R(RES)) ; LN applied on the fly via row stats.
#define STGW 7680u   /* words per stage: 3 arrays * 128 * 20 */
#define GEMM_SMEM (2u * STGW * 4u)   /* 61440 B dynamic */

__global__ __launch_bounds__(256, 2) void gemm_f16x2(
    const float* __restrict__ A, const __half* __restrict__ W,
    const float* __restrict__ bias, const float* __restrict__ RES,
    const float2* __restrict__ Ast, const float* __restrict__ Ag, const float* __restrict__ Abt,
    const float2* __restrict__ Rst, const float* __restrict__ Rg, const float* __restrict__ Rbt,
    float* __restrict__ C, __half* __restrict__ C16,
    int M, int N, int kLen, int ldk, int relu)
{
    extern __shared__ uint32_t sm[];   // [2][ Ah(2560) | Al(2560) | Ws(2560) ]
    __shared__ float2 sst[128];

    int tid = threadIdx.x;
    int wid = tid >> 5, lane = tid & 31;
    int grp = lane >> 2, tig = lane & 3;
    int wm = (wid >> 2) * 64;
    int wn = (wid & 3) * 32;
    int bm = blockIdx.y * 128, bn = blockIdx.x * 128;

    float acc[4][4][4];
    #pragma unroll
    for (int i = 0; i < 4; i++)
        #pragma unroll
        for (int j = 0; j < 4; j++)
            #pragma unroll
            for (int r = 0; r < 4; r++) acc[i][j][r] = 0.0f;

    const int ldr = tid >> 3;          // 0..31 (+32*i)
    const int ldw = (tid & 7) << 1;    // word col 0,2,..,14
    const int nk = kLen >> 5;

    if (Ast && tid < 128) sst[tid] = Ast[bm + tid];

    float4 pa[4];
    uint2  pw[4];

    auto do_load = [&](int k0) {
        #pragma unroll
        for (int i = 0; i < 4; i++) {
            int row = ldr + 32 * i;
            pa[i] = *(const float4*)(A + (size_t)(bm + row) * ldk + k0 + (ldw << 1));
            pw[i] = *(const uint2*)(W + (size_t)(bn + row) * ldk + k0 + (ldw << 1));
        }
    };
    auto do_store = [&](int s, int k0) {
        uint32_t* base = sm + (uint32_t)s * STGW;
        float4 gk, bk;
        if (Ast) {
            gk = *(const float4*)(Ag + k0 + (ldw << 1));
            bk = *(const float4*)(Abt + k0 + (ldw << 1));
        }
        #pragma unroll
        for (int i = 0; i < 4; i++) {
            int row = ldr + 32 * i;
            float4 v = pa[i];
            if (Ast) {
                float2 st = sst[row];
                v.x = (v.x - st.x) * st.y * gk.x + bk.x;
                v.y = (v.y - st.x) * st.y * gk.y + bk.y;
                v.z = (v.z - st.x) * st.y * gk.z + bk.z;
                v.w = (v.w - st.x) * st.y * gk.w + bk.w;
            }
            uint32_t h0, l0, h1, l1;
            cvt_split2u(v.x, v.y, h0, l0);
            cvt_split2u(v.z, v.w, h1, l1);
            *(uint2*)&base[row * 20 + ldw]        = make_uint2(h0, h1);
            *(uint2*)&base[2560 + row * 20 + ldw] = make_uint2(l0, l1);
            *(uint2*)&base[5120 + row * 20 + ldw] = pw[i];
        }
    };

    do_load(0);
    __syncthreads();                   // sst ready
    do_store(0, 0);

    for (int it = 0; it < nk; it++) {
        __syncthreads();
        if (it + 1 < nk) do_load((it + 1) << 5);

        uint32_t* ab = sm + (uint32_t)(it & 1) * STGW;
        uint32_t* lb = ab + 2560;
        uint32_t* wb2 = ab + 5120;

        #pragma unroll
        for (int wb = 0; wb < 16; wb += 8) {
            uint32_t ah[4][4], al[4][4];
            #pragma unroll
            for (int mf = 0; mf < 4; mf++) {
                int m = wm + mf * 16 + grp;
                ah[mf][0] = ab[m * 20 + wb + tig];
                ah[mf][1] = ab[(m + 8) * 20 + wb + tig];
                ah[mf][2] = ab[m * 20 + wb + 4 + tig];
                ah[mf][3] = ab[(m + 8) * 20 + wb + 4 + tig];
                al[mf][0] = lb[m * 20 + wb + tig];
                al[mf][1] = lb[(m + 8) * 20 + wb + tig];
                al[mf][2] = lb[m * 20 + wb + 4 + tig];
                al[mf][3] = lb[(m + 8) * 20 + wb + 4 + tig];
            }
            #pragma unroll
            for (int nf = 0; nf < 4; nf++) {
                int n = wn + nf * 8 + grp;
                uint32_t bh[2];
                bh[0] = wb2[n * 20 + wb + tig];
                bh[1] = wb2[n * 20 + wb + 4 + tig];
                #pragma unroll
                for (int mf = 0; mf < 4; mf++) {
                    mma_f16(acc[mf][nf], ah[mf], bh);
                    mma_f16(acc[mf][nf], al[mf], bh);
                }
            }
        }

        if (it + 1 < nk) do_store((it + 1) & 1, (it + 1) << 5);
    }

    #pragma unroll
    for (int mf = 0; mf < 4; mf++) {
        int m = bm + wm + mf * 16 + grp;
        #pragma unroll
        for (int nf = 0; nf < 4; nf++) {
            int n = bn + wn + nf * 8 + tig * 2;
            float b0 = bias ? bias[n] : 0.0f;
            float b1 = bias ? bias[n + 1] : 0.0f;
            float v0 = acc[mf][nf][0] + b0;
            float v1 = acc[mf][nf][1] + b1;
            float v2 = acc[mf][nf][2] + b0;
            float v3 = acc[mf][nf][3] + b1;
            size_t o0 = (size_t)m * N + n, o1 = (size_t)(m + 8) * N + n;
            if (C16) {
                *(__half2*)&C16[o0] = __floats2half2_rn(v0, v1);
                *(__half2*)&C16[o1] = __floats2half2_rn(v2, v3);
            } else {
                if (RES) {
                    float2 r0 = *(const float2*)&RES[o0];
                    float2 r1 = *(const float2*)&RES[o1];
                    if (Rst) {
                        float2 s0v = Rst[m];
                        float2 s1v = Rst[m + 8];
                        float2 gv = *(const float2*)&Rg[n];
                        float2 bv = *(const float2*)&Rbt[n];
                        r0.x = (r0.x - s0v.x) * s0v.y * gv.x + bv.x;
                        r0.y = (r0.y - s0v.x) * s0v.y * gv.y + bv.y;
                        r1.x = (r1.x - s1v.x) * s1v.y * gv.x + bv.x;
                        r1.y = (r1.y - s1v.x) * s1v.y * gv.y + bv.y;
                    }
                    v0 += r0.x; v1 += r0.y; v2 += r1.x; v3 += r1.y;
                }
                if (relu) {
                    v0 = fmaxf(v0, 0.0f); v1 = fmaxf(v1, 0.0f);
                    v2 = fmaxf(v2, 0.0f); v3 = fmaxf(v3, 0.0f);
                }
                *(float2*)&C[o0] = make_float2(v0, v1);
                *(float2*)&C[o1] = make_float2(v2, v3);
            }
        }
    }
}

// ---------------- row stats (mean, rstd) — same reduction as ln_kernel -----------
__global__ __launch_bounds__(256) void stats_kernel(const float* __restrict__ src,
                                                    float2* __restrict__ st) {
    int wid = threadIdx.x >> 5, lane = threadIdx.x & 31;
    size_t row = (size_t)blockIdx.x * 8 + wid;
    size_t base = row * 256;
    int c0 = lane * 4, c1 = 128 + lane * 4;
    float4 a0 = *(const float4*)&src[base + c0];
    float4 a1 = *(const float4*)&src[base + c1];
    float t[8] = { a0.x, a0.y, a0.z, a0.w, a1.x, a1.y, a1.z, a1.w };
    float s = 0.0f;
    #pragma unroll
    for (int i = 0; i < 8; i++) s += t[i];
    #pragma unroll
    for (int off = 16; off; off >>= 1) s += __shfl_xor_sync(0xffffffffu, s, off);
    float mean = s * (1.0f / 256.0f);
    float v = 0.0f;
    #pragma unroll
    for (int i = 0; i < 8; i++) { t[i] -= mean; v += t[i] * t[i]; }
    #pragma unroll
    for (int off = 16; off; off >>= 1) v += __shfl_xor_sync(0xffffffffu, v, off);
    float rstd = rsqrtf(v * (1.0f / 256.0f) + 1e-5f);
    if (lane == 0) st[row] = make_float2(mean, rstd);
}

// ---------------- materializing layernorm (final layer only) ----------------
__global__ __launch_bounds__(256) void ln_kernel(float* __restrict__ x,
                                                 const float* __restrict__ src,
                                                 const float* __restrict__ gg,
                                                 const float* __restrict__ bb) {
    int wid = threadIdx.x >> 5, lane = threadIdx.x & 31;
    size_t base = ((size_t)blockIdx.x * 8 + wid) * 256;
    int c0 = lane * 4, c1 = 128 + lane * 4;
    float4 a0 = *(const float4*)&src[base + c0];
    float4 a1 = *(const float4*)&src[base + c1];
    float t[8] = { a0.x, a0.y, a0.z, a0.w, a1.x, a1.y, a1.z, a1.w };
    float s = 0.0f;
    #pragma unroll
    for (int i = 0; i < 8; i++) s += t[i];
    #pragma unroll
    for (int off = 16; off; off >>= 1) s += __shfl_xor_sync(0xffffffffu, s, off);
    float mean = s * (1.0f / 256.0f);
    float v = 0.0f;
    #pragma unroll
    for (int i = 0; i < 8; i++) { t[i] -= mean; v += t[i] * t[i]; }
    #pragma unroll
    for (int off = 16; off; off >>= 1) v += __shfl_xor_sync(0xffffffffu, v, off);
    float rstd = rsqrtf(v * (1.0f / 256.0f) + 1e-5f);
    float4 g0 = *(const float4*)&gg[c0];
    float4 g1 = *(const float4*)&gg[c1];
    float4 e0 = *(const float4*)&bb[c0];
    float4 e1 = *(const float4*)&bb[c1];
    float4 r0 = make_float4(t[0] * rstd * g0.x + e0.x, t[1] * rstd * g0.y + e0.y,
                            t[2] * rstd * g0.z + e0.z, t[3] * rstd * g0.w + e0.w);
    float4 r1 = make_float4(t[4] * rstd * g1.x + e1.x, t[5] * rstd * g1.y + e1.y,
                            t[6] * rstd * g1.z + e1.z, t[7] * rstd * g1.w + e1.w);
    *(float4*)&x[base + c0] = r0;
    *(float4*)&x[base + c1] = r1;
}

// ---------------- split-K combine ----------------
__global__ void combine_relu_kernel(const float* __restrict__ a,
                                    const float* __restrict__ b,
                                    const float* __restrict__ bias,
                                    float* __restrict__ out) {
    int idx = blockIdx.x * 256 + threadIdx.x;
    int col = (idx * 4) & 1023;
    float4 va = ((const float4*)a)[idx];
    float4 vb = ((const float4*)b)[idx];
    float4 r;
    r.x = fmaxf(va.x + vb.x + bias[col],     0.0f);
    r.y = fmaxf(va.y + vb.y + bias[col + 1], 0.0f);
    r.z = fmaxf(va.z + vb.z + bias[col + 2], 0.0f);
    r.w = fmaxf(va.w + vb.w + bias[col + 3], 0.0f);
    ((float4*)out)[idx] = r;
}

// ---------------- tensor-core attention (proven) ----------------
#define AQ 0u
#define AK 5120u
#define AV 10240u
#define ATTN_SMEM (14848u * 4u)

__global__ __launch_bounds__(256, 2) void attn_mma_kernel(const __half* __restrict__ qkv,
                                                          float* __restrict__ o) {
    extern __shared__ uint32_t smw[];
    int b = blockIdx.x >> 1;
    int h0 = (blockIdx.x & 1) * 4;
    int tid = threadIdx.x;
    int wid = tid >> 5, lane = tid & 31;
    int grp = lane >> 2, tig = lane & 3;

    const float scale = 0.17677669529663687f;

    #pragma unroll
    for (int it = 0; it < 8; it++) {
        int idx = it * 256 + tid;
        int hh = idx >> 9;
        int r = (idx >> 3) & 63;
        int j4 = idx & 7;
        size_t base = ((size_t)b * 64 + r) * 768 + (h0 + hh) * 32 + j4 * 4;
        uint2 qw = *(const uint2*)&qkv[base];
        uint2 kw = *(const uint2*)&qkv[base + 256];
        uint2 vw = *(const uint2*)&qkv[base + 512];
        int qb = hh * 1280 + r * 20 + j4 * 2;
        smw[AQ + qb] = qw.x; smw[AQ + qb + 1] = qw.y;
        smw[AK + qb] = kw.x; smw[AK + qb + 1] = kw.y;
        __half* vp = (__half*)(smw + AV) + hh * 2304;
        __half2 v01 = *(__half2*)&vw.x;
        __half2 v23 = *(__half2*)&vw.y;
        vp[(j4 * 4 + 0) * 72 + r] = __low2half(v01);
        vp[(j4 * 4 + 1) * 72 + r] = __high2half(v01);
        vp[(j4 * 4 + 2) * 72 + r] = __low2half(v23);
        vp[(j4 * 4 + 3) * 72 + r] = __high2half(v23);
    }
    __syncthreads();

    int hh = wid >> 1;
    int mfb = (wid & 1) * 2;
    const uint32_t q0 = AQ + hh * 1280;
    const uint32_t k0 = AK + hh * 1280;
    const uint32_t v0 = AV + hh * 1152;

    float O[2][4][4];
    #pragma unroll
    for (int i = 0; i < 2; i++)
        #pragma unroll
        for (int j = 0; j < 4; j++)
            #pragma unroll
            for (int r = 0; r < 4; r++) O[i][j][r] = 0.0f;

    #pragma unroll
    for (int mi = 0; mi < 2; mi++) {
        int mf = mfb + mi;
        float S[8][4];
        #pragma unroll
        for (int nf = 0; nf < 8; nf++)
            #pragma unroll
            for (int r = 0; r < 4; r++) S[nf][r] = 0.0f;

        #pragma unroll
        for (int kc = 0; kc < 2; kc++) {
            int rA = mf * 16 + grp;
            uint32_t a[4];
            a[0] = smw[q0 + rA * 20 + kc * 8 + tig];
            a[1] = smw[q0 + (rA + 8) * 20 + kc * 8 + tig];
            a[2] = smw[q0 + rA * 20 + kc * 8 + 4 + tig];
            a[3] = smw[q0 + (rA + 8) * 20 + kc * 8 + 4 + tig];
            #pragma unroll
            for (int nf = 0; nf < 8; nf++) {
                int rB = nf * 8 + grp;
                uint32_t bb[2];
                bb[0] = smw[k0 + rB * 20 + kc * 8 + tig];
                bb[1] = smw[k0 + rB * 20 + kc * 8 + 4 + tig];
                mma_f16(S[nf], a, bb);
            }
        }

        float m0 = -1e30f, m1 = -1e30f;
        #pragma unroll
        for (int nf = 0; nf < 8; nf++) {
            m0 = fmaxf(m0, fmaxf(S[nf][0], S[nf][1]));
            m1 = fmaxf(m1, fmaxf(S[nf][2], S[nf][3]));
        }
        m0 = fmaxf(m0, __shfl_xor_sync(0xffffffffu, m0, 1));
        m0 = fmaxf(m0, __shfl_xor_sync(0xffffffffu, m0, 2));
        m1 = fmaxf(m1, __shfl_xor_sync(0xffffffffu, m1, 1));
        m1 = fmaxf(m1, __shfl_xor_sync(0xffffffffu, m1, 2));
        float s0 = 0.0f, s1 = 0.0f;
        #pragma unroll
        for (int nf = 0; nf < 8; nf++) {
            S[nf][0] = __expf((S[nf][0] - m0) * scale); s0 += S[nf][0];
            S[nf][1] = __expf((S[nf][1] - m0) * scale); s0 += S[nf][1];
            S[nf][2] = __expf((S[nf][2] - m1) * scale); s1 += S[nf][2];
            S[nf][3] = __expf((S[nf][3] - m1) * scale); s1 += S[nf][3];
        }
        s0 += __shfl_xor_sync(0xffffffffu, s0, 1);
        s0 += __shfl_xor_sync(0xffffffffu, s0, 2);
        s1 += __shfl_xor_sync(0xffffffffu, s1, 1);
        s1 += __shfl_xor_sync(0xffffffffu, s1, 2);
        float i0 = 1.0f / s0, i1 = 1.0f / s1;

        uint32_t PHa[8], PHb[8];
        #pragma unroll
        for (int nf = 0; nf < 8; nf++) {
            PHa[nf] = packh(S[nf][0] * i0, S[nf][1] * i0);
            PHb[nf] = packh(S[nf][2] * i1, S[nf][3] * i1);
        }

        #pragma unroll
        for (int jc = 0; jc < 4; jc++) {
            uint32_t a2[4] = { PHa[2 * jc], PHb[2 * jc], PHa[2 * jc + 1], PHb[2 * jc + 1] };
            #pragma unroll
            for (int no = 0; no < 4; no++) {
                int rB = no * 8 + grp;
                uint32_t bv[2];
                bv[0] = smw[v0 + rB * 36 + jc * 8 + tig];
                bv[1] = smw[v0 + rB * 36 + jc * 8 + 4 + tig];
                mma_f16(O[mi][no], a2, bv);
            }
        }
    }

    #pragma unroll
    for (int mi = 0; mi < 2; mi++) {
        int row = (mfb + mi) * 16 + grp;
        #pragma unroll
        for (int no = 0; no < 4; no++) {
            int d = no * 8 + tig * 2;
            size_t ob = ((size_t)b * 64 + row) * DM + (h0 + hh) * 32 + d;
            *(float2*)&o[ob]          = make_float2(O[mi][no][0], O[mi][no][1]);
            *(float2*)&o[ob + 8 * DM] = make_float2(O[mi][no][2], O[mi][no][3]);
        }
    }
}

// ---------------- mean pooling ----------------
__global__ void pool_kernel(const float* __restrict__ x, float* __restrict__ pooled) {
    int b = blockIdx.x, d = threadIdx.x;
    float s = 0.0f;
    #pragma unroll 8
    for (int i = 0; i < 64; i++) s += x[((size_t)b * 64 + i) * DM + d];
    pooled[(size_t)b * DM + d] = s * (1.0f / 64.0f);
}

// ---------------- tiny head finals ----------------
__global__ void head_final_kernel(const float* __restrict__ hid,
                                  const float* __restrict__ w,
                                  const float* __restrict__ bias,
                                  float* __restrict__ out, int nout, int do_tanh) {
    int b = blockIdx.x;
    int lane = threadIdx.x;
    for (int o = 0; o < nout; o++) {
        float s = 0.0f;
        #pragma unroll
        for (int i = lane; i < 256; i += 32) s = fmaf(hid[(size_t)b * 256 + i], w[o * 256 + i], s);
        #pragma unroll
        for (int off = 16; off; off >>= 1) s += __shfl_xor_sync(0xffffffffu, s, off);
        if (lane == 0) {
            float v = s + bias[o];
            out[(size_t)b * nout + o] = do_tanh ? tanhf(v) : v;
        }
    }
}

// ---------------- host side ----------------
static inline void sgemm(const float* A, const __half* W, const float* bias,
                         const float* res,
                         const float2* Ast, const float* Ag, const float* Abt,
                         const float2* Rst, const float* Rg, const float* Rbt,
                         float* C, __half* C16,
                         int M, int N, int kLen, int ldk, int relu) {
    dim3 g(N / 128, M / 128), blk(256);
    gemm_f16x2<<<g, blk, GEMM_SMEM>>>(A, W, bias, res, Ast, Ag, Abt, Rst, Rg, Rbt,
                                      C, C16, M, N, kLen, ldk, relu);
}

static inline void wcvt(const float* in, __half* o, size_t n) {
    int n4 = (int)(n / 4);
    wcvt_kernel<<<(n4 + 255) / 256, 256>>>(in, o, n4);
}

extern "C" void kernel_launch(void* const* d_in, const int* in_sizes, int n_in,
                              void* d_out, int out_size) {
    const float* board = (const float*)d_in[0];
    const float* emb   = (const float*)d_in[1];
    const float* qkv_w = (const float*)d_in[2];
    const float* qkv_b = (const float*)d_in[3];
    const float* out_w = (const float*)d_in[4];
    const float* out_b = (const float*)d_in[5];
    const float* ln1_g = (const float*)d_in[6];
    const float* ln1_b = (const float*)d_in[7];
    const float* ln2_g = (const float*)d_in[8];
    const float* ln2_b = (const float*)d_in[9];
    const float* ff1_w = (const float*)d_in[10];
    const float* ff1_b = (const float*)d_in[11];
    const float* ff2_w = (const float*)d_in[12];
    const float* ff2_b = (const float*)d_in[13];
    const float* vw1 = (const float*)d_in[14];
    const float* vb1 = (const float*)d_in[15];
    const float* vw2 = (const float*)d_in[16];
    const float* vb2 = (const float*)d_in[17];
    const float* pw1 = (const float*)d_in[18];
    const float* pb1 = (const float*)d_in[19];
    const float* pw2 = (const float*)d_in[20];
    const float* pb2 = (const float*)d_in[21];
    const float* cw1 = (const float*)d_in[22];
    const float* cb1 = (const float*)d_in[23];
    const float* cw2 = (const float*)d_in[24];
    const float* cb2 = (const float*)d_in[25];

    float* out = (float*)d_out;
    float* out_value  = out;
    float* out_policy = out + BATCH;
    float* out_class  = out + BATCH + (size_t)BATCH * 4096;

    cudaFuncSetAttribute(attn_mma_kernel, cudaFuncAttributeMaxDynamicSharedMemorySize,
                         ATTN_SMEM);
    cudaFuncSetAttribute(gemm_f16x2, cudaFuncAttributeMaxDynamicSharedMemorySize,
                         GEMM_SMEM);

    float *px, *po, *py, *pff, *ppe, *ppool, *pvh, *pch, *ph1, *ph1a, *ph1b;
    float2 *pst1, *pst2;
    __half *pqkv, *w16;
    cudaGetSymbolAddress((void**)&px,    g_x);
    cudaGetSymbolAddress((void**)&pqkv,  g_qkv16);
    cudaGetSymbolAddress((void**)&po,    g_o);
    cudaGetSymbolAddress((void**)&py,    g_y);
    cudaGetSymbolAddress((void**)&pff,   g_ffb);
    cudaGetSymbolAddress((void**)&ppe,   g_pe);
    cudaGetSymbolAddress((void**)&ppool, g_pooled);
    cudaGetSymbolAddress((void**)&pvh,   g_vh);
    cudaGetSymbolAddress((void**)&pch,   g_ch);
    cudaGetSymbolAddress((void**)&ph1,   g_h1);
    cudaGetSymbolAddress((void**)&ph1a,  g_h1a);
    cudaGetSymbolAddress((void**)&ph1b,  g_h1b);
    cudaGetSymbolAddress((void**)&pst1,  g_st1);
    cudaGetSymbolAddress((void**)&pst2,  g_st2);
    cudaGetSymbolAddress((void**)&w16,   g_w16);

    wcvt(qkv_w, w16 + OFF_QKV, 6UL * 768 * 256);
    wcvt(out_w, w16 + OFF_OUT, 6UL * 256 * 256);
    wcvt(ff1_w, w16 + OFF_FF1, 6UL * 1024 * 256);
    wcvt(ff2_w, w16 + OFF_FF2, 6UL * 256 * 1024);
    wcvt(vw1,   w16 + OFF_VW1, 256UL * 256);
    wcvt(cw1,   w16 + OFF_CW1, 256UL * 256);
    wcvt(pw1,   w16 + OFF_PW1, 1024UL * 16384);
    wcvt(pw2,   w16 + OFF_PW2, 4096UL * 1024);

    pe_kernel<<<SQ, DM>>>(ppe);
    embed_kernel<<<MTOK, DM>>>(board, emb, ppe, px);

    for (int l = 0; l < NL; l++) {
        const __half* Wqkv = w16 + OFF_QKV + (size_t)l * 768 * 256;
        const __half* Wout = w16 + OFF_OUT + (size_t)l * 256 * 256;
        const __half* W1   = w16 + OFF_FF1 + (size_t)l * 1024 * 256;
        const __half* W2   = w16 + OFF_FF2 + (size_t)l * 256 * 1024;
        // LN params of PREVIOUS layer's ln2 apply to the current y2 stream (g_x)
        const float2* st2  = (l == 0) ? 0 : pst2;
        const float*  g2p  = (l == 0) ? 0 : ln2_g + (size_t)(l - 1) * DM;
        const float*  b2p  = (l == 0) ? 0 : ln2_b + (size_t)(l - 1) * DM;

        // qkv = LN(y2) @ Wqkv^T
        sgemm(px, Wqkv, qkv_b + (size_t)l * 768, 0, st2, g2p, b2p, 0, 0, 0,
              0, pqkv, MTOK, 768, 256, 256, 0);
        attn_mma_kernel<<<BATCH * 2, 256, ATTN_SMEM>>>(pqkv, po);
        // y1 = LN(y2) + o @ Wout^T
        sgemm(po, Wout, out_b + (size_t)l * 256, px, 0, 0, 0, st2, g2p, b2p,
              py, 0, MTOK, 256, 256, 256, 0);
        stats_kernel<<<MTOK / 8, 256>>>(py, pst1);
        // ff = relu(LN(y1) @ W1^T)
        sgemm(py, W1, ff1_b + (size_t)l * 1024, 0, pst1, ln1_g + (size_t)l * DM,
              ln1_b + (size_t)l * DM, 0, 0, 0, pff, 0, MTOK, 1024, 256, 256, 1);
        // y2' = LN(y1) + ff @ W2^T
        sgemm(pff, W2, ff2_b + (size_t)l * 256, py, 0, 0, 0, pst1,
              ln1_g + (size_t)l * DM, ln1_b + (size_t)l * DM,
              px, 0, MTOK, 256, 1024, 1024, 0);
        if (l < NL - 1) stats_kernel<<<MTOK / 8, 256>>>(px, pst2);
    }

    // materialize final x = LN(y2, ln2[5]) into g_o
    ln_kernel<<<MTOK / 8, 256>>>(po, px, ln2_g + 5 * DM, ln2_b + 5 * DM);

    // heads
    pool_kernel<<<BATCH, DM>>>(po, ppool);

    sgemm(ppool, w16 + OFF_VW1, vb1, 0, 0, 0, 0, 0, 0, 0, pvh, 0,
          BATCH, 256, 256, 256, 1);
    head_final_kernel<<<BATCH, 32>>>(pvh, vw2, vb2, out_value, 1, 1);

    // policy: split-K=2 over K=16384 (final x viewed as [B, 64*256])
    sgemm(po,        w16 + OFF_PW1,        0, 0, 0, 0, 0, 0, 0, 0, ph1a, 0,
          BATCH, 1024, 8192, 16384, 0);
    sgemm(po + 8192, w16 + OFF_PW1 + 8192, 0, 0, 0, 0, 0, 0, 0, 0, ph1b, 0,
          BATCH, 1024, 8192, 16384, 0);
    combine_relu_kernel<<<BATCH * 1024 / 4 / 256, 256>>>(ph1a, ph1b, pb1, ph1);
    sgemm(ph1, w16 + OFF_PW2, pb2, 0, 0, 0, 0, 0, 0, 0, out_policy, 0,
          BATCH, 4096, 1024, 1024, 0);

    sgemm(ppool, w16 + OFF_CW1, cb1, 0, 0, 0, 0, 0, 0, 0, pch, 0,
          BATCH, 256, 256, 256, 1);
    head_final_kernel<<<BATCH, 32>>>(pch, cw2, cb2, out_class, 3, 0);
}

// round 16
// speedup vs baseline: 1.0645x; 1.0645x over previous
#include <cuda_runtime.h>
#include <cuda_fp16.h>
#include <math.h>
#include <stdint.h>

#define BATCH 4096
#define SQ    64
#define DM    256
#define NH    8
#define FFD   1024
#define NL    6
#define MTOK  (BATCH*SQ)   /* 262144 */

// ---------------- scratch (no allocations allowed) ----------------
__device__ float  g_x[MTOK*DM];
__device__ __align__(16) __half g_qkv16[MTOK*3*DM];
__device__ float  g_o[MTOK*DM];
__device__ float  g_y[MTOK*DM];
__device__ float  g_ffb[MTOK*FFD];
__device__ float  g_pe[SQ*DM];
__device__ float  g_pooled[BATCH*DM];
__device__ float  g_vh[BATCH*DM];
__device__ float  g_ch[BATCH*DM];
__device__ float  g_h1[BATCH*1024];
__device__ float  g_h1a[BATCH*1024];
__device__ float  g_h1b[BATCH*1024];

// fp16 weight pool (offsets in halfs)
#define OFF_QKV 0UL
#define OFF_OUT 1179648UL
#define OFF_FF1 1572864UL
#define OFF_FF2 3145728UL
#define OFF_VW1 4718592UL
#define OFF_CW1 4784128UL
#define OFF_PW1 4849664UL
#define OFF_PW2 21626880UL
#define WPOOL   25821184UL
__device__ __align__(16) __half g_w16[WPOOL];

// ---------------- fp16 helpers ----------------
__device__ __forceinline__ uint32_t packh(float a, float b) {
    __half2 t = __floats2half2_rn(a, b);
    return *(uint32_t*)&t;
}

__device__ __forceinline__ void cvt_split2u(float x, float y, uint32_t& hi, uint32_t& lo) {
    __half hx = __float2half(x);
    __half hy = __float2half(y);
    hi = ((uint32_t)__half_as_ushort(hy) << 16) | (uint32_t)__half_as_ushort(hx);
    lo = packh(x - __half2float(hx), y - __half2float(hy));
}

__device__ __forceinline__ void mma_f16(float* c, const uint32_t* a, const uint32_t* b) {
    asm volatile(
        "mma.sync.aligned.m16n8k16.row.col.f32.f16.f16.f32 "
        "{%0,%1,%2,%3}, {%4,%5,%6,%7}, {%8,%9}, {%0,%1,%2,%3};\n"
        : "+f"(c[0]), "+f"(c[1]), "+f"(c[2]), "+f"(c[3])
        : "r"(a[0]), "r"(a[1]), "r"(a[2]), "r"(a[3]), "r"(b[0]), "r"(b[1]));
}

__device__ __forceinline__ void ldsm4(uint32_t& r0, uint32_t& r1, uint32_t& r2, uint32_t& r3,
                                      uint32_t a) {
    asm volatile("ldmatrix.sync.aligned.m8n8.x4.shared.b16 {%0,%1,%2,%3}, [%4];"
                 : "=r"(r0), "=r"(r1), "=r"(r2), "=r"(r3) : "r"(a));
}

// ---------------- weight fp32 -> fp16 (rn; bit-identical to in-kernel cvt) ---------
__global__ void wcvt_kernel(const float* __restrict__ in, __half* __restrict__ o, int n4) {
    int i = blockIdx.x * 256 + threadIdx.x;
    if (i >= n4) return;
    float4 v = ((const float4*)in)[i];
    uint2 w = make_uint2(packh(v.x, v.y), packh(v.z, v.w));
    *(uint2*)&o[(size_t)i * 4] = w;
}

// ---------------- PE precompute ----------------
__global__ void pe_kernel(float* __restrict__ pe) {
    int s = blockIdx.x, d = threadIdx.x;
    int row = s >> 3, col = s & 7;
    int m = d >> 1;
    float div = powf(10000.0f, (2.0f * (float)m) / 256.0f);
    float v = (d & 1) ? cosf((float)col / div) : sinf((float)row / div);
    pe[s * DM + d] = v;
}

// ---------------- tokens + embedding + PE ----------------
__global__ void embed_kernel(const float* __restrict__ board,
                             const float* __restrict__ emb,
                             const float* __restrict__ pe,
                             float* __restrict__ x) {
    int tokidx = blockIdx.x;
    int b = tokidx >> 6, s = tokidx & 63;
    __shared__ float ch[14];
    __shared__ int tok;
    int d = threadIdx.x;
    if (d < 14) ch[d] = board[(size_t)b * 896 + (size_t)d * 64 + s];
    __syncthreads();
    if (d == 0) {
        float mx = ch[0]; int idx = 0;
        #pragma unroll
        for (int c = 1; c < 14; c++) { if (ch[c] > mx) { mx = ch[c]; idx = c; } }
        tok = (mx > 0.0f) ? (idx + 1) : 0;
    }
    __syncthreads();
    x[(size_t)tokidx * DM + d] = emb[tok * DM + d] + pe[s * DM + d];
}

// ---------------- fp16 2-term GEMM, double-buffered + ldmatrix fragments -----------
// C[M,N] = A[M,K] @ W[N,K]^T + bias;  D = (Ah + Al) * W16, fp32 accum.
// A fp32 (split in-kernel), W pre-converted fp16. 2-stage smem pipeline,
// one __syncthreads per k32 iteration; fragments via ldmatrix.x4.
#define STGW 7680u   /* words per stage: 3 arrays * 128 * 20 */
#define GEMM_SMEM (2u * STGW * 4u)   /* 61440 B */

__global__ __launch_bounds__(256, 2) void gemm_f16x2(
    const float* __restrict__ A, const __half* __restrict__ W,
    const float* __restrict__ bias, const float* __restrict__ RES,
    float* __restrict__ C, __half* __restrict__ C16,
    int M, int N, int kLen, int ldk, int relu)
{
    extern __shared__ uint32_t sm[];   // [2][ Ah(2560) | Al(2560) | Ws(2560) ]
    uint32_t smu = (uint32_t)__cvta_generic_to_shared(sm);

    int tid = threadIdx.x;
    int wid = tid >> 5, lane = tid & 31;
    int grp = lane >> 2, tig = lane & 3;
    int r15 = lane & 15, seg = lane >> 4;
    int wm = (wid >> 2) * 64;
    int wn = (wid & 3) * 32;
    int bm = blockIdx.y * 128, bn = blockIdx.x * 128;

    float acc[4][4][4];
    #pragma unroll
    for (int i = 0; i < 4; i++)
        #pragma unroll
        for (int j = 0; j < 4; j++)
            #pragma unroll
            for (int r = 0; r < 4; r++) acc[i][j][r] = 0.0f;

    const int ldr = tid >> 3;          // 0..31 (+32*i)
    const int ldw = (tid & 7) << 1;    // word col 0,2,..,14
    const int nk = kLen >> 5;

    float4 pa[4];
    uint2  pw[4];

    auto do_load = [&](int k0) {
        #pragma unroll
        for (int i = 0; i < 4; i++) {
            int row = ldr + 32 * i;
            pa[i] = *(const float4*)(A + (size_t)(bm + row) * ldk + k0 + (ldw << 1));
            pw[i] = *(const uint2*)(W + (size_t)(bn + row) * ldk + k0 + (ldw << 1));
        }
    };
    auto do_store = [&](int s) {
        uint32_t* base = sm + (uint32_t)s * STGW;
        #pragma unroll
        for (int i = 0; i < 4; i++) {
            int row = ldr + 32 * i;
            uint32_t h0, l0, h1, l1;
            cvt_split2u(pa[i].x, pa[i].y, h0, l0);
            cvt_split2u(pa[i].z, pa[i].w, h1, l1);
            *(uint2*)&base[row * 20 + ldw]        = make_uint2(h0, h1);
            *(uint2*)&base[2560 + row * 20 + ldw] = make_uint2(l0, l1);
            *(uint2*)&base[5120 + row * 20 + ldw] = pw[i];
        }
    };

    do_load(0);
    do_store(0);

    for (int it = 0; it < nk; it++) {
        __syncthreads();
        if (it + 1 < nk) do_load((it + 1) << 5);

        uint32_t ab = smu + ((uint32_t)(it & 1) * STGW) * 4u;
        uint32_t lb = ab + 2560u * 4u;
        uint32_t wb2 = ab + 5120u * 4u;

        #pragma unroll
        for (int wb = 0; wb < 16; wb += 8) {
            uint32_t ah[4][4], al[4][4], bh[4][2];
            #pragma unroll
            for (int mf = 0; mf < 4; mf++) {
                uint32_t off = (uint32_t)(((wm + mf * 16 + r15) * 20 + wb + seg * 4) * 4);
                ldsm4(ah[mf][0], ah[mf][1], ah[mf][2], ah[mf][3], ab + off);
                ldsm4(al[mf][0], al[mf][1], al[mf][2], al[mf][3], lb + off);
            }
            #pragma unroll
            for (int hf = 0; hf < 2; hf++) {
                uint32_t off = (uint32_t)(((wn + hf * 16 + r15) * 20 + wb + seg * 4) * 4);
                uint32_t t0, t1, t2, t3;
                ldsm4(t0, t1, t2, t3, wb2 + off);
                bh[hf * 2][0] = t0;     bh[hf * 2][1] = t2;
                bh[hf * 2 + 1][0] = t1; bh[hf * 2 + 1][1] = t3;
            }
            #pragma unroll
            for (int nf = 0; nf < 4; nf++)
                #pragma unroll
                for (int mf = 0; mf < 4; mf++) {
                    mma_f16(acc[mf][nf], ah[mf], bh[nf]);
                    mma_f16(acc[mf][nf], al[mf], bh[nf]);
                }
        }

        if (it + 1 < nk) do_store((it + 1) & 1);
    }

    #pragma unroll
    for (int mf = 0; mf < 4; mf++) {
        int m = bm + wm + mf * 16 + grp;
        #pragma unroll
        for (int nf = 0; nf < 4; nf++) {
            int n = bn + wn + nf * 8 + tig * 2;
            float b0 = bias ? bias[n] : 0.0f;
            float b1 = bias ? bias[n + 1] : 0.0f;
            float v0 = acc[mf][nf][0] + b0;
            float v1 = acc[mf][nf][1] + b1;
            float v2 = acc[mf][nf][2] + b0;
            float v3 = acc[mf][nf][3] + b1;
            size_t o0 = (size_t)m * N + n, o1 = (size_t)(m + 8) * N + n;
            if (C16) {
                *(__half2*)&C16[o0] = __floats2half2_rn(v0, v1);
                *(__half2*)&C16[o1] = __floats2half2_rn(v2, v3);
            } else {
                if (RES) {
                    float2 r0 = *(const float2*)&RES[o0];
                    float2 r1 = *(const float2*)&RES[o1];
                    v0 += r0.x; v1 += r0.y; v2 += r1.x; v3 += r1.y;
                }
                if (relu) {
                    v0 = fmaxf(v0, 0.0f); v1 = fmaxf(v1, 0.0f);
                    v2 = fmaxf(v2, 0.0f); v3 = fmaxf(v3, 0.0f);
                }
                *(float2*)&C[o0] = make_float2(v0, v1);
                *(float2*)&C[o1] = make_float2(v2, v3);
            }
        }
    }
}

// ---------------- split-K combine: out = relu(a + b + bias) ----------------
__global__ void combine_relu_kernel(const float* __restrict__ a,
                                    const float* __restrict__ b,
                                    const float* __restrict__ bias,
                                    float* __restrict__ out) {
    int idx = blockIdx.x * 256 + threadIdx.x;
    int col = (idx * 4) & 1023;
    float4 va = ((const float4*)a)[idx];
    float4 vb = ((const float4*)b)[idx];
    float4 r;
    r.x = fmaxf(va.x + vb.x + bias[col],     0.0f);
    r.y = fmaxf(va.y + vb.y + bias[col + 1], 0.0f);
    r.z = fmaxf(va.z + vb.z + bias[col + 2], 0.0f);
    r.w = fmaxf(va.w + vb.w + bias[col + 3], 0.0f);
    ((float4*)out)[idx] = r;
}

// ---------------- tensor-core attention (round-11/12 proven) ----------------
#define AQ 0u
#define AK 5120u
#define AV 10240u
#define ATTN_SMEM (14848u * 4u)   /* 59392 B */

__global__ __launch_bounds__(256, 2) void attn_mma_kernel(const __half* __restrict__ qkv,
                                                          float* __restrict__ o) {
    extern __shared__ uint32_t smw[];
    int b = blockIdx.x >> 1;
    int h0 = (blockIdx.x & 1) * 4;
    int tid = threadIdx.x;
    int wid = tid >> 5, lane = tid & 31;
    int grp = lane >> 2, tig = lane & 3;

    const float scale = 0.17677669529663687f;

    #pragma unroll
    for (int it = 0; it < 8; it++) {
        int idx = it * 256 + tid;
        int hh = idx >> 9;
        int r = (idx >> 3) & 63;
        int j4 = idx & 7;
        size_t base = ((size_t)b * 64 + r) * 768 + (h0 + hh) * 32 + j4 * 4;
        uint2 qw = *(const uint2*)&qkv[base];
        uint2 kw = *(const uint2*)&qkv[base + 256];
        uint2 vw = *(const uint2*)&qkv[base + 512];
        int qb = hh * 1280 + r * 20 + j4 * 2;
        smw[AQ + qb] = qw.x; smw[AQ + qb + 1] = qw.y;
        smw[AK + qb] = kw.x; smw[AK + qb + 1] = kw.y;
        __half* vp = (__half*)(smw + AV) + hh * 2304;
        __half2 v01 = *(__half2*)&vw.x;
        __half2 v23 = *(__half2*)&vw.y;
        vp[(j4 * 4 + 0) * 72 + r] = __low2half(v01);
        vp[(j4 * 4 + 1) * 72 + r] = __high2half(v01);
        vp[(j4 * 4 + 2) * 72 + r] = __low2half(v23);
        vp[(j4 * 4 + 3) * 72 + r] = __high2half(v23);
    }
    __syncthreads();

    int hh = wid >> 1;
    int mfb = (wid & 1) * 2;
    const uint32_t q0 = AQ + hh * 1280;
    const uint32_t k0 = AK + hh * 1280;
    const uint32_t v0 = AV + hh * 1152;

    float O[2][4][4];
    #pragma unroll
    for (int i = 0; i < 2; i++)
        #pragma unroll
        for (int j = 0; j < 4; j++)
            #pragma unroll
            for (int r = 0; r < 4; r++) O[i][j][r] = 0.0f;

    #pragma unroll
    for (int mi = 0; mi < 2; mi++) {
        int mf = mfb + mi;
        float S[8][4];
        #pragma unroll
        for (int nf = 0; nf < 8; nf++)
            #pragma unroll
            for (int r = 0; r < 4; r++) S[nf][r] = 0.0f;

        #pragma unroll
        for (int kc = 0; kc < 2; kc++) {
            int rA = mf * 16 + grp;
            uint32_t a[4];
            a[0] = smw[q0 + rA * 20 + kc * 8 + tig];
            a[1] = smw[q0 + (rA + 8) * 20 + kc * 8 + tig];
            a[2] = smw[q0 + rA * 20 + kc * 8 + 4 + tig];
            a[3] = smw[q0 + (rA + 8) * 20 + kc * 8 + 4 + tig];
            #pragma unroll
            for (int nf = 0; nf < 8; nf++) {
                int rB = nf * 8 + grp;
                uint32_t bb[2];
                bb[0] = smw[k0 + rB * 20 + kc * 8 + tig];
                bb[1] = smw[k0 + rB * 20 + kc * 8 + 4 + tig];
                mma_f16(S[nf], a, bb);
            }
        }

        float m0 = -1e30f, m1 = -1e30f;
        #pragma unroll
        for (int nf = 0; nf < 8; nf++) {
            m0 = fmaxf(m0, fmaxf(S[nf][0], S[nf][1]));
            m1 = fmaxf(m1, fmaxf(S[nf][2], S[nf][3]));
        }
        m0 = fmaxf(m0, __shfl_xor_sync(0xffffffffu, m0, 1));
        m0 = fmaxf(m0, __shfl_xor_sync(0xffffffffu, m0, 2));
        m1 = fmaxf(m1, __shfl_xor_sync(0xffffffffu, m1, 1));
        m1 = fmaxf(m1, __shfl_xor_sync(0xffffffffu, m1, 2));
        float s0 = 0.0f, s1 = 0.0f;
        #pragma unroll
        for (int nf = 0; nf < 8; nf++) {
            S[nf][0] = __expf((S[nf][0] - m0) * scale); s0 += S[nf][0];
            S[nf][1] = __expf((S[nf][1] - m0) * scale); s0 += S[nf][1];
            S[nf][2] = __expf((S[nf][2] - m1) * scale); s1 += S[nf][2];
            S[nf][3] = __expf((S[nf][3] - m1) * scale); s1 += S[nf][3];
        }
        s0 += __shfl_xor_sync(0xffffffffu, s0, 1);
        s0 += __shfl_xor_sync(0xffffffffu, s0, 2);
        s1 += __shfl_xor_sync(0xffffffffu, s1, 1);
        s1 += __shfl_xor_sync(0xffffffffu, s1, 2);
        float i0 = 1.0f / s0, i1 = 1.0f / s1;

        uint32_t PHa[8], PHb[8];
        #pragma unroll
        for (int nf = 0; nf < 8; nf++) {
            PHa[nf] = packh(S[nf][0] * i0, S[nf][1] * i0);
            PHb[nf] = packh(S[nf][2] * i1, S[nf][3] * i1);
        }

        #pragma unroll
        for (int jc = 0; jc < 4; jc++) {
            uint32_t a2[4] = { PHa[2 * jc], PHb[2 * jc], PHa[2 * jc + 1], PHb[2 * jc + 1] };
            #pragma unroll
            for (int no = 0; no < 4; no++) {
                int rB = no * 8 + grp;
                uint32_t bv[2];
                bv[0] = smw[v0 + rB * 36 + jc * 8 + tig];
                bv[1] = smw[v0 + rB * 36 + jc * 8 + 4 + tig];
                mma_f16(O[mi][no], a2, bv);
            }
        }
    }

    #pragma unroll
    for (int mi = 0; mi < 2; mi++) {
        int row = (mfb + mi) * 16 + grp;
        #pragma unroll
        for (int no = 0; no < 4; no++) {
            int d = no * 8 + tig * 2;
            size_t ob = ((size_t)b * 64 + row) * DM + (h0 + hh) * 32 + d;
            *(float2*)&o[ob]          = make_float2(O[mi][no][0], O[mi][no][1]);
            *(float2*)&o[ob + 8 * DM] = make_float2(O[mi][no][2], O[mi][no][3]);
        }
    }
}

// ---------------- layernorm (input already contains residual): warp per row ---------
__global__ __launch_bounds__(256) void ln_kernel(float* __restrict__ x,
                                                 const float* __restrict__ src,
                                                 const float* __restrict__ gg,
                                                 const float* __restrict__ bb) {
    int wid = threadIdx.x >> 5, lane = threadIdx.x & 31;
    size_t base = ((size_t)blockIdx.x * 8 + wid) * 256;
    int c0 = lane * 4, c1 = 128 + lane * 4;
    float4 a0 = *(const float4*)&src[base + c0];
    float4 a1 = *(const float4*)&src[base + c1];
    float t[8] = { a0.x, a0.y, a0.z, a0.w, a1.x, a1.y, a1.z, a1.w };
    float s = 0.0f;
    #pragma unroll
    for (int i = 0; i < 8; i++) s += t[i];
    #pragma unroll
    for (int off = 16; off; off >>= 1) s += __shfl_xor_sync(0xffffffffu, s, off);
    float mean = s * (1.0f / 256.0f);
    float v = 0.0f;
    #pragma unroll
    for (int i = 0; i < 8; i++) { t[i] -= mean; v += t[i] * t[i]; }
    #pragma unroll
    for (int off = 16; off; off >>= 1) v += __shfl_xor_sync(0xffffffffu, v, off);
    float rstd = rsqrtf(v * (1.0f / 256.0f) + 1e-5f);
    float4 g0 = *(const float4*)&gg[c0];
    float4 g1 = *(const float4*)&gg[c1];
    float4 e0 = *(const float4*)&bb[c0];
    float4 e1 = *(const float4*)&bb[c1];
    float4 r0 = make_float4(t[0] * rstd * g0.x + e0.x, t[1] * rstd * g0.y + e0.y,
                            t[2] * rstd * g0.z + e0.z, t[3] * rstd * g0.w + e0.w);
    float4 r1 = make_float4(t[4] * rstd * g1.x + e1.x, t[5] * rstd * g1.y + e1.y,
                            t[6] * rstd * g1.z + e1.z, t[7] * rstd * g1.w + e1.w);
    *(float4*)&x[base + c0] = r0;
    *(float4*)&x[base + c1] = r1;
}

// ---------------- mean pooling ----------------
__global__ void pool_kernel(const float* __restrict__ x, float* __restrict__ pooled) {
    int b = blockIdx.x, d = threadIdx.x;
    float s = 0.0f;
    #pragma unroll 8
    for (int i = 0; i < 64; i++) s += x[((size_t)b * 64 + i) * DM + d];
    pooled[(size_t)b * DM + d] = s * (1.0f / 64.0f);
}

// ---------------- tiny head finals ----------------
__global__ void head_final_kernel(const float* __restrict__ hid,
                                  const float* __restrict__ w,
                                  const float* __restrict__ bias,
                                  float* __restrict__ out, int nout, int do_tanh) {
    int b = blockIdx.x;
    int lane = threadIdx.x;
    for (int o = 0; o < nout; o++) {
        float s = 0.0f;
        #pragma unroll
        for (int i = lane; i < 256; i += 32) s = fmaf(hid[(size_t)b * 256 + i], w[o * 256 + i], s);
        #pragma unroll
        for (int off = 16; off; off >>= 1) s += __shfl_xor_sync(0xffffffffu, s, off);
        if (lane == 0) {
            float v = s + bias[o];
            out[(size_t)b * nout + o] = do_tanh ? tanhf(v) : v;
        }
    }
}

// ---------------- host side ----------------
static inline void sgemm(const float* A, const __half* W, const float* bias,
                         const float* res, float* C, __half* C16,
                         int M, int N, int kLen, int ldk, int relu) {
    dim3 g(N / 128, M / 128), blk(256);
    gemm_f16x2<<<g, blk, GEMM_SMEM>>>(A, W, bias, res, C, C16, M, N, kLen, ldk, relu);
}

static inline void wcvt(const float* in, __half* o, size_t n) {
    int n4 = (int)(n / 4);
    wcvt_kernel<<<(n4 + 255) / 256, 256>>>(in, o, n4);
}

extern "C" void kernel_launch(void* const* d_in, const int* in_sizes, int n_in,
                              void* d_out, int out_size) {
    const float* board = (const float*)d_in[0];
    const float* emb   = (const float*)d_in[1];
    const float* qkv_w = (const float*)d_in[2];
    const float* qkv_b = (const float*)d_in[3];
    const float* out_w = (const float*)d_in[4];
    const float* out_b = (const float*)d_in[5];
    const float* ln1_g = (const float*)d_in[6];
    const float* ln1_b = (const float*)d_in[7];
    const float* ln2_g = (const float*)d_in[8];
    const float* ln2_b = (const float*)d_in[9];
    const float* ff1_w = (const float*)d_in[10];
    const float* ff1_b = (const float*)d_in[11];
    const float* ff2_w = (const float*)d_in[12];
    const float* ff2_b = (const float*)d_in[13];
    const float* vw1 = (const float*)d_in[14];
    const float* vb1 = (const float*)d_in[15];
    const float* vw2 = (const float*)d_in[16];
    const float* vb2 = (const float*)d_in[17];
    const float* pw1 = (const float*)d_in[18];
    const float* pb1 = (const float*)d_in[19];
    const float* pw2 = (const float*)d_in[20];
    const float* pb2 = (const float*)d_in[21];
    const float* cw1 = (const float*)d_in[22];
    const float* cb1 = (const float*)d_in[23];
    const float* cw2 = (const float*)d_in[24];
    const float* cb2 = (const float*)d_in[25];

    float* out = (float*)d_out;
    float* out_value  = out;
    float* out_policy = out + BATCH;
    float* out_class  = out + BATCH + (size_t)BATCH * 4096;

    cudaFuncSetAttribute(attn_mma_kernel, cudaFuncAttributeMaxDynamicSharedMemorySize,
                         ATTN_SMEM);
    cudaFuncSetAttribute(gemm_f16x2, cudaFuncAttributeMaxDynamicSharedMemorySize,
                         GEMM_SMEM);

    float *px, *po, *py, *pff, *ppe, *ppool, *pvh, *pch, *ph1, *ph1a, *ph1b;
    __half *pqkv, *w16;
    cudaGetSymbolAddress((void**)&px,    g_x);
    cudaGetSymbolAddress((void**)&pqkv,  g_qkv16);
    cudaGetSymbolAddress((void**)&po,    g_o);
    cudaGetSymbolAddress((void**)&py,    g_y);
    cudaGetSymbolAddress((void**)&pff,   g_ffb);
    cudaGetSymbolAddress((void**)&ppe,   g_pe);
    cudaGetSymbolAddress((void**)&ppool, g_pooled);
    cudaGetSymbolAddress((void**)&pvh,   g_vh);
    cudaGetSymbolAddress((void**)&pch,   g_ch);
    cudaGetSymbolAddress((void**)&ph1,   g_h1);
    cudaGetSymbolAddress((void**)&ph1a,  g_h1a);
    cudaGetSymbolAddress((void**)&ph1b,  g_h1b);
    cudaGetSymbolAddress((void**)&w16,   g_w16);

    // one-time weight conversions (bit-identical rn rounding)
    wcvt(qkv_w, w16 + OFF_QKV, 6UL * 768 * 256);
    wcvt(out_w, w16 + OFF_OUT, 6UL * 256 * 256);
    wcvt(ff1_w, w16 + OFF_FF1, 6UL * 1024 * 256);
    wcvt(ff2_w, w16 + OFF_FF2, 6UL * 256 * 1024);
    wcvt(vw1,   w16 + OFF_VW1, 256UL * 256);
    wcvt(cw1,   w16 + OFF_CW1, 256UL * 256);
    wcvt(pw1,   w16 + OFF_PW1, 1024UL * 16384);
    wcvt(pw2,   w16 + OFF_PW2, 4096UL * 1024);

    pe_kernel<<<SQ, DM>>>(ppe);
    embed_kernel<<<MTOK, DM>>>(board, emb, ppe, px);

    for (int l = 0; l < NL; l++) {
        const __half* Wqkv = w16 + OFF_QKV + (size_t)l * 768 * 256;
        const __half* Wout = w16 + OFF_OUT + (size_t)l * 256 * 256;
        const __half* W1   = w16 + OFF_FF1 + (size_t)l * 1024 * 256;
        const __half* W2   = w16 + OFF_FF2 + (size_t)l * 256 * 1024;

        sgemm(px, Wqkv, qkv_b + (size_t)l * 768, 0, 0, pqkv, MTOK, 768, 256, 256, 0);
        attn_mma_kernel<<<BATCH * 2, 256, ATTN_SMEM>>>(pqkv, po);
        sgemm(po, Wout, out_b + (size_t)l * 256, px, py, 0, MTOK, 256, 256, 256, 0);
        ln_kernel<<<MTOK / 8, 256>>>(px, py, ln1_g + l * DM, ln1_b + l * DM);
        sgemm(px, W1, ff1_b + (size_t)l * 1024, 0, pff, 0, MTOK, 1024, 256, 256, 1);
        sgemm(pff, W2, ff2_b + (size_t)l * 256, px, py, 0, MTOK, 256, 1024, 1024, 0);
        ln_kernel<<<MTOK / 8, 256>>>(px, py, ln2_g + l * DM, ln2_b + l * DM);
    }

    // heads
    pool_kernel<<<BATCH, DM>>>(px, ppool);

    sgemm(ppool, w16 + OFF_VW1, vb1, 0, pvh, 0, BATCH, 256, 256, 256, 1);
    head_final_kernel<<<BATCH, 32>>>(pvh, vw2, vb2, out_value, 1, 1);

    // policy: split-K=2 over K=16384 (x viewed as [B, 64*256])
    sgemm(px,        w16 + OFF_PW1,        0, 0, ph1a, 0, BATCH, 1024, 8192, 16384, 0);
    sgemm(px + 8192, w16 + OFF_PW1 + 8192, 0, 0, ph1b, 0, BATCH, 1024, 8192, 16384, 0);
    combine_relu_kernel<<<BATCH * 1024 / 4 / 256, 256>>>(ph1a, ph1b, pb1, ph1);
    sgemm(ph1, w16 + OFF_PW2, pb2, 0, out_policy, 0, BATCH, 4096, 1024, 1024, 0);

    sgemm(ppool, w16 + OFF_CW1, cb1, 0, pch, 0, BATCH, 256, 256, 256, 1);
    head_final_kernel<<<BATCH, 32>>>(pch, cw2, cb2, out_class, 3, 0);
}

// round 17
// speedup vs baseline: 1.2109x; 1.1375x over previous
#include <cuda_runtime.h>
#include <cuda_fp16.h>
#include <math.h>
#include <stdint.h>

#define BATCH 4096
#define SQ    64
#define DM    256
#define NH    8
#define FFD   1024
#define NL    6
#define MTOK  (BATCH*SQ)   /* 262144 */

// ---------------- scratch (no allocations allowed) ----------------
__device__ float  g_x[MTOK*DM];
__device__ __align__(16) __half g_qkv16[MTOK*3*DM];
__device__ __align__(16) __half g_o16[MTOK*DM];
__device__ float  g_y[MTOK*DM];
__device__ __align__(16) __half g_ffb16[MTOK*FFD];
__device__ float  g_pe[SQ*DM];
__device__ float  g_pooled[BATCH*DM];
__device__ float  g_vh[BATCH*DM];
__device__ float  g_ch[BATCH*DM];
__device__ float  g_h1[BATCH*1024];
__device__ float  g_h1a[BATCH*1024];
__device__ float  g_h1b[BATCH*1024];

// fp16 weight pool (offsets in halfs)
#define OFF_QKV 0UL
#define OFF_OUT 1179648UL
#define OFF_FF1 1572864UL
#define OFF_FF2 3145728UL
#define OFF_VW1 4718592UL
#define OFF_CW1 4784128UL
#define OFF_PW1 4849664UL
#define OFF_PW2 21626880UL
#define WPOOL   25821184UL
__device__ __align__(16) __half g_w16[WPOOL];

// ---------------- fp16 helpers ----------------
__device__ __forceinline__ uint32_t packh(float a, float b) {
    __half2 t = __floats2half2_rn(a, b);
    return *(uint32_t*)&t;
}

__device__ __forceinline__ void cvt_split2u(float x, float y, uint32_t& hi, uint32_t& lo) {
    __half hx = __float2half(x);
    __half hy = __float2half(y);
    hi = ((uint32_t)__half_as_ushort(hy) << 16) | (uint32_t)__half_as_ushort(hx);
    lo = packh(x - __half2float(hx), y - __half2float(hy));
}

__device__ __forceinline__ void mma_f16(float* c, const uint32_t* a, const uint32_t* b) {
    asm volatile(
        "mma.sync.aligned.m16n8k16.row.col.f32.f16.f16.f32 "
        "{%0,%1,%2,%3}, {%4,%5,%6,%7}, {%8,%9}, {%0,%1,%2,%3};\n"
        : "+f"(c[0]), "+f"(c[1]), "+f"(c[2]), "+f"(c[3])
        : "r"(a[0]), "r"(a[1]), "r"(a[2]), "r"(a[3]), "r"(b[0]), "r"(b[1]));
}

// ---------------- weight fp32 -> fp16 ----------------
__global__ void wcvt_kernel(const float* __restrict__ in, __half* __restrict__ o, int n4) {
    int i = blockIdx.x * 256 + threadIdx.x;
    if (i >= n4) return;
    float4 v = ((const float4*)in)[i];
    uint2 w = make_uint2(packh(v.x, v.y), packh(v.z, v.w));
    *(uint2*)&o[(size_t)i * 4] = w;
}

// ---------------- PE precompute ----------------
__global__ void pe_kernel(float* __restrict__ pe) {
    int s = blockIdx.x, d = threadIdx.x;
    int row = s >> 3, col = s & 7;
    int m = d >> 1;
    float div = powf(10000.0f, (2.0f * (float)m) / 256.0f);
    float v = (d & 1) ? cosf((float)col / div) : sinf((float)row / div);
    pe[s * DM + d] = v;
}

// ---------------- tokens + embedding + PE ----------------
__global__ void embed_kernel(const float* __restrict__ board,
                             const float* __restrict__ emb,
                             const float* __restrict__ pe,
                             float* __restrict__ x) {
    int tokidx = blockIdx.x;
    int b = tokidx >> 6, s = tokidx & 63;
    __shared__ float ch[14];
    __shared__ int tok;
    int d = threadIdx.x;
    if (d < 14) ch[d] = board[(size_t)b * 896 + (size_t)d * 64 + s];
    __syncthreads();
    if (d == 0) {
        float mx = ch[0]; int idx = 0;
        #pragma unroll
        for (int c = 1; c < 14; c++) { if (ch[c] > mx) { mx = ch[c]; idx = c; } }
        tok = (mx > 0.0f) ? (idx + 1) : 0;
    }
    __syncthreads();
    x[(size_t)tokidx * DM + d] = emb[tok * DM + d] + pe[s * DM + d];
}

// ---------------- fp16 2-term GEMM, double-buffered (round-14 proven) --------------
// D = (Ah + Al) * W16, fp32 accum. A fp32, split in-kernel; W fp16 pool.
#define STGW 7680u
#define GEMM_SMEM (2u * STGW * 4u)   /* 61440 B dynamic */

__global__ __launch_bounds__(256, 2) void gemm_f16x2(
    const float* __restrict__ A, const __half* __restrict__ W,
    const float* __restrict__ bias, const float* __restrict__ RES,
    float* __restrict__ C, __half* __restrict__ C16,
    int M, int N, int kLen, int ldk, int relu)
{
    extern __shared__ uint32_t sm[];

    int tid = threadIdx.x;
    int wid = tid >> 5, lane = tid & 31;
    int grp = lane >> 2, tig = lane & 3;
    int wm = (wid >> 2) * 64;
    int wn = (wid & 3) * 32;
    int bm = blockIdx.y * 128, bn = blockIdx.x * 128;

    float acc[4][4][4];
    #pragma unroll
    for (int i = 0; i < 4; i++)
        #pragma unroll
        for (int j = 0; j < 4; j++)
            #pragma unroll
            for (int r = 0; r < 4; r++) acc[i][j][r] = 0.0f;

    const int ldr = tid >> 3;
    const int ldw = (tid & 7) << 1;
    const int nk = kLen >> 5;

    float4 pa[4];
    uint2  pw[4];

    auto do_load = [&](int k0) {
        #pragma unroll
        for (int i = 0; i < 4; i++) {
            int row = ldr + 32 * i;
            pa[i] = *(const float4*)(A + (size_t)(bm + row) * ldk + k0 + (ldw << 1));
            pw[i] = *(const uint2*)(W + (size_t)(bn + row) * ldk + k0 + (ldw << 1));
        }
    };
    auto do_store = [&](int s) {
        uint32_t* base = sm + (uint32_t)s * STGW;
        #pragma unroll
        for (int i = 0; i < 4; i++) {
            int row = ldr + 32 * i;
            uint32_t h0, l0, h1, l1;
            cvt_split2u(pa[i].x, pa[i].y, h0, l0);
            cvt_split2u(pa[i].z, pa[i].w, h1, l1);
            *(uint2*)&base[row * 20 + ldw]        = make_uint2(h0, h1);
            *(uint2*)&base[2560 + row * 20 + ldw] = make_uint2(l0, l1);
            *(uint2*)&base[5120 + row * 20 + ldw] = pw[i];
        }
    };

    do_load(0);
    do_store(0);

    for (int it = 0; it < nk; it++) {
        __syncthreads();
        if (it + 1 < nk) do_load((it + 1) << 5);

        uint32_t* ab = sm + (uint32_t)(it & 1) * STGW;
        uint32_t* lb = ab + 2560;
        uint32_t* wb2 = ab + 5120;

        #pragma unroll
        for (int wb = 0; wb < 16; wb += 8) {
            uint32_t ah[4][4], al[4][4];
            #pragma unroll
            for (int mf = 0; mf < 4; mf++) {
                int m = wm + mf * 16 + grp;
                ah[mf][0] = ab[m * 20 + wb + tig];
                ah[mf][1] = ab[(m + 8) * 20 + wb + tig];
                ah[mf][2] = ab[m * 20 + wb + 4 + tig];
                ah[mf][3] = ab[(m + 8) * 20 + wb + 4 + tig];
                al[mf][0] = lb[m * 20 + wb + tig];
                al[mf][1] = lb[(m + 8) * 20 + wb + tig];
                al[mf][2] = lb[m * 20 + wb + 4 + tig];
                al[mf][3] = lb[(m + 8) * 20 + wb + 4 + tig];
            }
            #pragma unroll
            for (int nf = 0; nf < 4; nf++) {
                int n = wn + nf * 8 + grp;
                uint32_t bh[2];
                bh[0] = wb2[n * 20 + wb + tig];
                bh[1] = wb2[n * 20 + wb + 4 + tig];
                #pragma unroll
                for (int mf = 0; mf < 4; mf++) {
                    mma_f16(acc[mf][nf], ah[mf], bh);
                    mma_f16(acc[mf][nf], al[mf], bh);
                }
            }
        }

        if (it + 1 < nk) do_store((it + 1) & 1);
    }

    #pragma unroll
    for (int mf = 0; mf < 4; mf++) {
        int m = bm + wm + mf * 16 + grp;
        #pragma unroll
        for (int nf = 0; nf < 4; nf++) {
            int n = bn + wn + nf * 8 + tig * 2;
            float b0 = bias ? bias[n] : 0.0f;
            float b1 = bias ? bias[n + 1] : 0.0f;
            float v0 = acc[mf][nf][0] + b0;
            float v1 = acc[mf][nf][1] + b1;
            float v2 = acc[mf][nf][2] + b0;
            float v3 = acc[mf][nf][3] + b1;
            size_t o0 = (size_t)m * N + n, o1 = (size_t)(m + 8) * N + n;
            if (relu) {
                v0 = fmaxf(v0, 0.0f); v1 = fmaxf(v1, 0.0f);
                v2 = fmaxf(v2, 0.0f); v3 = fmaxf(v3, 0.0f);
            }
            if (C16) {
                *(__half2*)&C16[o0] = __floats2half2_rn(v0, v1);
                *(__half2*)&C16[o1] = __floats2half2_rn(v2, v3);
            } else {
                if (RES) {
                    float2 r0 = *(const float2*)&RES[o0];
                    float2 r1 = *(const float2*)&RES[o1];
                    v0 += r0.x; v1 += r0.y; v2 += r1.x; v3 += r1.y;
                }
                *(float2*)&C[o0] = make_float2(v0, v1);
                *(float2*)&C[o1] = make_float2(v2, v3);
            }
        }
    }
}

// ---------------- fp16 1-term GEMM (A already fp16), double-buffered ---------------
// D = A16 * W16, fp32 accum. Used for out-proj (A=attn out) and ff2 (A=hidden).
#define STGA 5120u   /* words per stage: 2 arrays * 128 * 20 */

__global__ __launch_bounds__(256, 2) void gemm_f16a(
    const __half* __restrict__ A, const __half* __restrict__ W,
    const float* __restrict__ bias, const float* __restrict__ RES,
    float* __restrict__ C, int M, int N, int kLen, int ldk)
{
    __shared__ uint32_t sm[2 * STGA];   // 40960 B static

    int tid = threadIdx.x;
    int wid = tid >> 5, lane = tid & 31;
    int grp = lane >> 2, tig = lane & 3;
    int wm = (wid >> 2) * 64;
    int wn = (wid & 3) * 32;
    int bm = blockIdx.y * 128, bn = blockIdx.x * 128;

    float acc[4][4][4];
    #pragma unroll
    for (int i = 0; i < 4; i++)
        #pragma unroll
        for (int j = 0; j < 4; j++)
            #pragma unroll
            for (int r = 0; r < 4; r++) acc[i][j][r] = 0.0f;

    const int ldr = tid >> 3;
    const int ldw = (tid & 7) << 1;
    const int nk = kLen >> 5;

    uint2 pa[4], pw[4];

    auto do_load = [&](int k0) {
        #pragma unroll
        for (int i = 0; i < 4; i++) {
            int row = ldr + 32 * i;
            pa[i] = *(const uint2*)(A + (size_t)(bm + row) * ldk + k0 + (ldw << 1));
            pw[i] = *(const uint2*)(W + (size_t)(bn + row) * ldk + k0 + (ldw << 1));
        }
    };
    auto do_store = [&](int s) {
        uint32_t* base = sm + (uint32_t)s * STGA;
        #pragma unroll
        for (int i = 0; i < 4; i++) {
            int row = ldr + 32 * i;
            *(uint2*)&base[row * 20 + ldw]        = pa[i];
            *(uint2*)&base[2560 + row * 20 + ldw] = pw[i];
        }
    };

    do_load(0);
    do_store(0);

    for (int it = 0; it < nk; it++) {
        __syncthreads();
        if (it + 1 < nk) do_load((it + 1) << 5);

        uint32_t* ab = sm + (uint32_t)(it & 1) * STGA;
        uint32_t* wb2 = ab + 2560;

        #pragma unroll
        for (int wb = 0; wb < 16; wb += 8) {
            uint32_t ah[4][4];
            #pragma unroll
            for (int mf = 0; mf < 4; mf++) {
                int m = wm + mf * 16 + grp;
                ah[mf][0] = ab[m * 20 + wb + tig];
                ah[mf][1] = ab[(m + 8) * 20 + wb + tig];
                ah[mf][2] = ab[m * 20 + wb + 4 + tig];
                ah[mf][3] = ab[(m + 8) * 20 + wb + 4 + tig];
            }
            #pragma unroll
            for (int nf = 0; nf < 4; nf++) {
                int n = wn + nf * 8 + grp;
                uint32_t bh[2];
                bh[0] = wb2[n * 20 + wb + tig];
                bh[1] = wb2[n * 20 + wb + 4 + tig];
                #pragma unroll
                for (int mf = 0; mf < 4; mf++)
                    mma_f16(acc[mf][nf], ah[mf], bh);
            }
        }

        if (it + 1 < nk) do_store((it + 1) & 1);
    }

    #pragma unroll
    for (int mf = 0; mf < 4; mf++) {
        int m = bm + wm + mf * 16 + grp;
        #pragma unroll
        for (int nf = 0; nf < 4; nf++) {
            int n = bn + wn + nf * 8 + tig * 2;
            float b0 = bias[n], b1 = bias[n + 1];
            float v0 = acc[mf][nf][0] + b0;
            float v1 = acc[mf][nf][1] + b1;
            float v2 = acc[mf][nf][2] + b0;
            float v3 = acc[mf][nf][3] + b1;
            size_t o0 = (size_t)m * N + n, o1 = (size_t)(m + 8) * N + n;
            float2 r0 = *(const float2*)&RES[o0];
            float2 r1 = *(const float2*)&RES[o1];
            v0 += r0.x; v1 += r0.y; v2 += r1.x; v3 += r1.y;
            *(float2*)&C[o0] = make_float2(v0, v1);
            *(float2*)&C[o1] = make_float2(v2, v3);
        }
    }
}

// ---------------- split-K combine ----------------
__global__ void combine_relu_kernel(const float* __restrict__ a,
                                    const float* __restrict__ b,
                                    const float* __restrict__ bias,
                                    float* __restrict__ out) {
    int idx = blockIdx.x * 256 + threadIdx.x;
    int col = (idx * 4) & 1023;
    float4 va = ((const float4*)a)[idx];
    float4 vb = ((const float4*)b)[idx];
    float4 r;
    r.x = fmaxf(va.x + vb.x + bias[col],     0.0f);
    r.y = fmaxf(va.y + vb.y + bias[col + 1], 0.0f);
    r.z = fmaxf(va.z + vb.z + bias[col + 2], 0.0f);
    r.w = fmaxf(va.w + vb.w + bias[col + 3], 0.0f);
    ((float4*)out)[idx] = r;
}

// ---------------- tensor-core attention (proven; fp16 output) ----------------
#define AQ 0u
#define AK 5120u
#define AV 10240u
#define ATTN_SMEM (14848u * 4u)

__global__ __launch_bounds__(256, 2) void attn_mma_kernel(const __half* __restrict__ qkv,
                                                          __half* __restrict__ o) {
    extern __shared__ uint32_t smw[];
    int b = blockIdx.x >> 1;
    int h0 = (blockIdx.x & 1) * 4;
    int tid = threadIdx.x;
    int wid = tid >> 5, lane = tid & 31;
    int grp = lane >> 2, tig = lane & 3;

    const float scale = 0.17677669529663687f;

    #pragma unroll
    for (int it = 0; it < 8; it++) {
        int idx = it * 256 + tid;
        int hh = idx >> 9;
        int r = (idx >> 3) & 63;
        int j4 = idx & 7;
        size_t base = ((size_t)b * 64 + r) * 768 + (h0 + hh) * 32 + j4 * 4;
        uint2 qw = *(const uint2*)&qkv[base];
        uint2 kw = *(const uint2*)&qkv[base + 256];
        uint2 vw = *(const uint2*)&qkv[base + 512];
        int qb = hh * 1280 + r * 20 + j4 * 2;
        smw[AQ + qb] = qw.x; smw[AQ + qb + 1] = qw.y;
        smw[AK + qb] = kw.x; smw[AK + qb + 1] = kw.y;
        __half* vp = (__half*)(smw + AV) + hh * 2304;
        __half2 v01 = *(__half2*)&vw.x;
        __half2 v23 = *(__half2*)&vw.y;
        vp[(j4 * 4 + 0) * 72 + r] = __low2half(v01);
        vp[(j4 * 4 + 1) * 72 + r] = __high2half(v01);
        vp[(j4 * 4 + 2) * 72 + r] = __low2half(v23);
        vp[(j4 * 4 + 3) * 72 + r] = __high2half(v23);
    }
    __syncthreads();

    int hh = wid >> 1;
    int mfb = (wid & 1) * 2;
    const uint32_t q0 = AQ + hh * 1280;
    const uint32_t k0 = AK + hh * 1280;
    const uint32_t v0 = AV + hh * 1152;

    float O[2][4][4];
    #pragma unroll
    for (int i = 0; i < 2; i++)
        #pragma unroll
        for (int j = 0; j < 4; j++)
            #pragma unroll
            for (int r = 0; r < 4; r++) O[i][j][r] = 0.0f;

    #pragma unroll
    for (int mi = 0; mi < 2; mi++) {
        int mf = mfb + mi;
        float S[8][4];
        #pragma unroll
        for (int nf = 0; nf < 8; nf++)
            #pragma unroll
            for (int r = 0; r < 4; r++) S[nf][r] = 0.0f;

        #pragma unroll
        for (int kc = 0; kc < 2; kc++) {
            int rA = mf * 16 + grp;
            uint32_t a[4];
            a[0] = smw[q0 + rA * 20 + kc * 8 + tig];
            a[1] = smw[q0 + (rA + 8) * 20 + kc * 8 + tig];
            a[2] = smw[q0 + rA * 20 + kc * 8 + 4 + tig];
            a[3] = smw[q0 + (rA + 8) * 20 + kc * 8 + 4 + tig];
            #pragma unroll
            for (int nf = 0; nf < 8; nf++) {
                int rB = nf * 8 + grp;
                uint32_t bb[2];
                bb[0] = smw[k0 + rB * 20 + kc * 8 + tig];
                bb[1] = smw[k0 + rB * 20 + kc * 8 + 4 + tig];
                mma_f16(S[nf], a, bb);
            }
        }

        float m0 = -1e30f, m1 = -1e30f;
        #pragma unroll
        for (int nf = 0; nf < 8; nf++) {
            m0 = fmaxf(m0, fmaxf(S[nf][0], S[nf][1]));
            m1 = fmaxf(m1, fmaxf(S[nf][2], S[nf][3]));
        }
        m0 = fmaxf(m0, __shfl_xor_sync(0xffffffffu, m0, 1));
        m0 = fmaxf(m0, __shfl_xor_sync(0xffffffffu, m0, 2));
        m1 = fmaxf(m1, __shfl_xor_sync(0xffffffffu, m1, 1));
        m1 = fmaxf(m1, __shfl_xor_sync(0xffffffffu, m1, 2));
        float s0 = 0.0f, s1 = 0.0f;
        #pragma unroll
        for (int nf = 0; nf < 8; nf++) {
            S[nf][0] = __expf((S[nf][0] - m0) * scale); s0 += S[nf][0];
            S[nf][1] = __expf((S[nf][1] - m0) * scale); s0 += S[nf][1];
            S[nf][2] = __expf((S[nf][2] - m1) * scale); s1 += S[nf][2];
            S[nf][3] = __expf((S[nf][3] - m1) * scale); s1 += S[nf][3];
        }
        s0 += __shfl_xor_sync(0xffffffffu, s0, 1);
        s0 += __shfl_xor_sync(0xffffffffu, s0, 2);
        s1 += __shfl_xor_sync(0xffffffffu, s1, 1);
        s1 += __shfl_xor_sync(0xffffffffu, s1, 2);
        float i0 = 1.0f / s0, i1 = 1.0f / s1;

        uint32_t PHa[8], PHb[8];
        #pragma unroll
        for (int nf = 0; nf < 8; nf++) {
            PHa[nf] = packh(S[nf][0] * i0, S[nf][1] * i0);
            PHb[nf] = packh(S[nf][2] * i1, S[nf][3] * i1);
        }

        #pragma unroll
        for (int jc = 0; jc < 4; jc++) {
            uint32_t a2[4] = { PHa[2 * jc], PHb[2 * jc], PHa[2 * jc + 1], PHb[2 * jc + 1] };
            #pragma unroll
            for (int no = 0; no < 4; no++) {
                int rB = no * 8 + grp;
                uint32_t bv[2];
                bv[0] = smw[v0 + rB * 36 + jc * 8 + tig];
                bv[1] = smw[v0 + rB * 36 + jc * 8 + 4 + tig];
                mma_f16(O[mi][no], a2, bv);
            }
        }
    }

    #pragma unroll
    for (int mi = 0; mi < 2; mi++) {
        int row = (mfb + mi) * 16 + grp;
        #pragma unroll
        for (int no = 0; no < 4; no++) {
            int d = no * 8 + tig * 2;
            size_t ob = ((size_t)b * 64 + row) * DM + (h0 + hh) * 32 + d;
            *(__half2*)&o[ob]          = __floats2half2_rn(O[mi][no][0], O[mi][no][1]);
            *(__half2*)&o[ob + 8 * DM] = __floats2half2_rn(O[mi][no][2], O[mi][no][3]);
        }
    }
}

// ---------------- layernorm: warp per row ----------------
__global__ __launch_bounds__(256) void ln_kernel(float* __restrict__ x,
                                                 const float* __restrict__ src,
                                                 const float* __restrict__ gg,
                                                 const float* __restrict__ bb) {
    int wid = threadIdx.x >> 5, lane = threadIdx.x & 31;
    size_t base = ((size_t)blockIdx.x * 8 + wid) * 256;
    int c0 = lane * 4, c1 = 128 + lane * 4;
    float4 a0 = *(const float4*)&src[base + c0];
    float4 a1 = *(const float4*)&src[base + c1];
    float t[8] = { a0.x, a0.y, a0.z, a0.w, a1.x, a1.y, a1.z, a1.w };
    float s = 0.0f;
    #pragma unroll
    for (int i = 0; i < 8; i++) s += t[i];
    #pragma unroll
    for (int off = 16; off; off >>= 1) s += __shfl_xor_sync(0xffffffffu, s, off);
    float mean = s * (1.0f / 256.0f);
    float v = 0.0f;
    #pragma unroll
    for (int i = 0; i < 8; i++) { t[i] -= mean; v += t[i] * t[i]; }
    #pragma unroll
    for (int off = 16; off; off >>= 1) v += __shfl_xor_sync(0xffffffffu, v, off);
    float rstd = rsqrtf(v * (1.0f / 256.0f) + 1e-5f);
    float4 g0 = *(const float4*)&gg[c0];
    float4 g1 = *(const float4*)&gg[c1];
    float4 e0 = *(const float4*)&bb[c0];
    float4 e1 = *(const float4*)&bb[c1];
    float4 r0 = make_float4(t[0] * rstd * g0.x + e0.x, t[1] * rstd * g0.y + e0.y,
                            t[2] * rstd * g0.z + e0.z, t[3] * rstd * g0.w + e0.w);
    float4 r1 = make_float4(t[4] * rstd * g1.x + e1.x, t[5] * rstd * g1.y + e1.y,
                            t[6] * rstd * g1.z + e1.z, t[7] * rstd * g1.w + e1.w);
    *(float4*)&x[base + c0] = r0;
    *(float4*)&x[base + c1] = r1;
}

// ---------------- mean pooling ----------------
__global__ void pool_kernel(const float* __restrict__ x, float* __restrict__ pooled) {
    int b = blockIdx.x, d = threadIdx.x;
    float s = 0.0f;
    #pragma unroll 8
    for (int i = 0; i < 64; i++) s += x[((size_t)b * 64 + i) * DM + d];
    pooled[(size_t)b * DM + d] = s * (1.0f / 64.0f);
}

// ---------------- tiny head finals ----------------
__global__ void head_final_kernel(const float* __restrict__ hid,
                                  const float* __restrict__ w,
                                  const float* __restrict__ bias,
                                  float* __restrict__ out, int nout, int do_tanh) {
    int b = blockIdx.x;
    int lane = threadIdx.x;
    for (int o = 0; o < nout; o++) {
        float s = 0.0f;
        #pragma unroll
        for (int i = lane; i < 256; i += 32) s = fmaf(hid[(size_t)b * 256 + i], w[o * 256 + i], s);
        #pragma unroll
        for (int off = 16; off; off >>= 1) s += __shfl_xor_sync(0xffffffffu, s, off);
        if (lane == 0) {
            float v = s + bias[o];
            out[(size_t)b * nout + o] = do_tanh ? tanhf(v) : v;
        }
    }
}

// ---------------- host side ----------------
static inline void sgemm(const float* A, const __half* W, const float* bias,
                         const float* res, float* C, __half* C16,
                         int M, int N, int kLen, int ldk, int relu) {
    dim3 g(N / 128, M / 128), blk(256);
    gemm_f16x2<<<g, blk, GEMM_SMEM>>>(A, W, bias, res, C, C16, M, N, kLen, ldk, relu);
}

static inline void sgemm_a(const __half* A, const __half* W, const float* bias,
                           const float* res, float* C,
                           int M, int N, int kLen, int ldk) {
    dim3 g(N / 128, M / 128), blk(256);
    gemm_f16a<<<g, blk>>>(A, W, bias, res, C, M, N, kLen, ldk);
}

static inline void wcvt(const float* in, __half* o, size_t n) {
    int n4 = (int)(n / 4);
    wcvt_kernel<<<(n4 + 255) / 256, 256>>>(in, o, n4);
}

extern "C" void kernel_launch(void* const* d_in, const int* in_sizes, int n_in,
                              void* d_out, int out_size) {
    const float* board = (const float*)d_in[0];
    const float* emb   = (const float*)d_in[1];
    const float* qkv_w = (const float*)d_in[2];
    const float* qkv_b = (const float*)d_in[3];
    const float* out_w = (const float*)d_in[4];
    const float* out_b = (const float*)d_in[5];
    const float* ln1_g = (const float*)d_in[6];
    const float* ln1_b = (const float*)d_in[7];
    const float* ln2_g = (const float*)d_in[8];
    const float* ln2_b = (const float*)d_in[9];
    const float* ff1_w = (const float*)d_in[10];
    const float* ff1_b = (const float*)d_in[11];
    const float* ff2_w = (const float*)d_in[12];
    const float* ff2_b = (const float*)d_in[13];
    const float* vw1 = (const float*)d_in[14];
    const float* vb1 = (const float*)d_in[15];
    const float* vw2 = (const float*)d_in[16];
    const float* vb2 = (const float*)d_in[17];
    const float* pw1 = (const float*)d_in[18];
    const float* pb1 = (const float*)d_in[19];
    const float* pw2 = (const float*)d_in[20];
    const float* pb2 = (const float*)d_in[21];
    const float* cw1 = (const float*)d_in[22];
    const float* cb1 = (const float*)d_in[23];
    const float* cw2 = (const float*)d_in[24];
    const float* cb2 = (const float*)d_in[25];

    float* out = (float*)d_out;
    float* out_value  = out;
    float* out_policy = out + BATCH;
    float* out_class  = out + BATCH + (size_t)BATCH * 4096;

    cudaFuncSetAttribute(attn_mma_kernel, cudaFuncAttributeMaxDynamicSharedMemorySize,
                         ATTN_SMEM);
    cudaFuncSetAttribute(gemm_f16x2, cudaFuncAttributeMaxDynamicSharedMemorySize,
                         GEMM_SMEM);

    float *px, *py, *ppe, *ppool, *pvh, *pch, *ph1, *ph1a, *ph1b;
    __half *pqkv, *po16, *pff16, *w16;
    cudaGetSymbolAddress((void**)&px,    g_x);
    cudaGetSymbolAddress((void**)&pqkv,  g_qkv16);
    cudaGetSymbolAddress((void**)&po16,  g_o16);
    cudaGetSymbolAddress((void**)&py,    g_y);
    cudaGetSymbolAddress((void**)&pff16, g_ffb16);
    cudaGetSymbolAddress((void**)&ppe,   g_pe);
    cudaGetSymbolAddress((void**)&ppool, g_pooled);
    cudaGetSymbolAddress((void**)&pvh,   g_vh);
    cudaGetSymbolAddress((void**)&pch,   g_ch);
    cudaGetSymbolAddress((void**)&ph1,   g_h1);
    cudaGetSymbolAddress((void**)&ph1a,  g_h1a);
    cudaGetSymbolAddress((void**)&ph1b,  g_h1b);
    cudaGetSymbolAddress((void**)&w16,   g_w16);

    // one-time weight conversions (bit-identical rn rounding)
    wcvt(qkv_w, w16 + OFF_QKV, 6UL * 768 * 256);
    wcvt(out_w, w16 + OFF_OUT, 6UL * 256 * 256);
    wcvt(ff1_w, w16 + OFF_FF1, 6UL * 1024 * 256);
    wcvt(ff2_w, w16 + OFF_FF2, 6UL * 256 * 1024);
    wcvt(vw1,   w16 + OFF_VW1, 256UL * 256);
    wcvt(cw1,   w16 + OFF_CW1, 256UL * 256);
    wcvt(pw1,   w16 + OFF_PW1, 1024UL * 16384);
    wcvt(pw2,   w16 + OFF_PW2, 4096UL * 1024);

    pe_kernel<<<SQ, DM>>>(ppe);
    embed_kernel<<<MTOK, DM>>>(board, emb, ppe, px);

    for (int l = 0; l < NL; l++) {
        const __half* Wqkv = w16 + OFF_QKV + (size_t)l * 768 * 256;
        const __half* Wout = w16 + OFF_OUT + (size_t)l * 256 * 256;
        const __half* W1   = w16 + OFF_FF1 + (size_t)l * 1024 * 256;
        const __half* W2   = w16 + OFF_FF2 + (size_t)l * 256 * 1024;

        sgemm(px, Wqkv, qkv_b + (size_t)l * 768, 0, 0, pqkv, MTOK, 768, 256, 256, 0);
        attn_mma_kernel<<<BATCH * 2, 256, ATTN_SMEM>>>(pqkv, po16);
        sgemm_a(po16, Wout, out_b + (size_t)l * 256, px, py, MTOK, 256, 256, 256);
        ln_kernel<<<MTOK / 8, 256>>>(px, py, ln1_g + l * DM, ln1_b + l * DM);
        sgemm(px, W1, ff1_b + (size_t)l * 1024, 0, 0, pff16, MTOK, 1024, 256, 256, 1);
        sgemm_a(pff16, W2, ff2_b + (size_t)l * 256, px, py, MTOK, 256, 1024, 1024);
        ln_kernel<<<MTOK / 8, 256>>>(px, py, ln2_g + l * DM, ln2_b + l * DM);
    }

    // heads
    pool_kernel<<<BATCH, DM>>>(px, ppool);

    sgemm(ppool, w16 + OFF_VW1, vb1, 0, pvh, 0, BATCH, 256, 256, 256, 1);
    head_final_kernel<<<BATCH, 32>>>(pvh, vw2, vb2, out_value, 1, 1);

    // policy: split-K=2 over K=16384 (x viewed as [B, 64*256])
    sgemm(px,        w16 + OFF_PW1,        0, 0, ph1a, 0, BATCH, 1024, 8192, 16384, 0);
    sgemm(px + 8192, w16 + OFF_PW1 + 8192, 0, 0, ph1b, 0, BATCH, 1024, 8192, 16384, 0);
    combine_relu_kernel<<<BATCH * 1024 / 4 / 256, 256>>>(ph1a, ph1b, pb1, ph1);
    sgemm(ph1, w16 + OFF_PW2, pb2, 0, out_policy, 0, BATCH, 4096, 1024, 1024, 0);

    sgemm(ppool, w16 + OFF_CW1, cb1, 0, pch, 0, BATCH, 256, 256, 256, 1);
    head_final_kernel<<<BATCH, 32>>>(pch, cw2, cb2, out_class, 3, 0);
}